// round 5
// baseline (speedup 1.0000x reference)
#include <cuda_runtime.h>

#define NROWS 65536
#define DIM   128
#define KCB   1024
#define NTILES 512            // row tiles of 128
#define NCHUNK 16             // K chunks of 64 codes
#define NUNITS (NTILES * NCHUNK)
#define NWORK  296            // persistent workers (148 SM x 2)

// ---------------- device scratch (no allocations allowed) ----------------
__device__ float              g_csum2[KCB];
__device__ int                g_counts[KCB];
__device__ double             g_loss;
__device__ unsigned long long g_best[NROWS];     // (dist_bits<<32)|code, atomicMin
__device__ int                g_chunkcnt[NTILES];

// ---------------- helpers ----------------
__device__ __forceinline__ unsigned long long ffma2(unsigned long long a,
                                                    unsigned long long b,
                                                    unsigned long long c) {
    unsigned long long d;
    asm("fma.rn.f32x2 %0, %1, %2, %3;" : "=l"(d) : "l"(a), "l"(b), "l"(c));
    return d;
}

__device__ __forceinline__ float2 u2f2(unsigned long long v) {
    union { unsigned long long u; float2 f; } cvt;
    cvt.u = v;
    return cvt.f;
}

// ---------------- prep: init scratch + codebook row sums ----------------
__global__ void vq_prep(const float* __restrict__ cb) {
    int k = blockIdx.x * blockDim.x + threadIdx.x;   // 64*256 = 16384 threads
    if (k < KCB) {
        g_counts[k] = 0;
        float s = 0.0f;
        const float* row = cb + (size_t)k * DIM;
        #pragma unroll 8
        for (int d = 0; d < DIM; d++) {
            float v = row[d];
            s = __fadd_rn(s, __fmul_rn(v, v));   // sequential order (kept fixed)
        }
        g_csum2[k] = s;
    }
    if (k < NTILES) g_chunkcnt[k] = 0;
    if (k == 0) g_loss = 0.0;
    #pragma unroll
    for (int i = 0; i < 4; i++)
        g_best[k + i * 16384] = 0xFFFFFFFFFFFFFFFFULL;
}

// ---------------- main persistent kernel ----------------
// 296 workers x 256 threads. Unit = (rowtile 128 rows) x (chunk of 64 codes).
// Worker w handles contiguous units [w*8192/296, (w+1)*8192/296): equal FLOPs.
// Thread tile: 8 rows x 4 codes, f32x2 packed along D.
#define B_STRIDE 132

__global__ void __launch_bounds__(256, 2)
vq_main(const float* __restrict__ in, const float* __restrict__ cb,
        float* __restrict__ out) {
    extern __shared__ float smem[];
    float* As      = smem;                          // 128*128 floats (unpadded)
    float* Bs      = smem + 128 * 128;              // 64*132 floats (reused for reduce)
    float* rows2_s = Bs + 64 * B_STRIDE;            // 128
    float* csum_s  = rows2_s + 128;                 // 64
    int*   besti_s = (int*)(csum_s + 64);           // 128
    int*   flag_s  = besti_s + 128;                 // 1
    float* redv    = Bs;                            // 128*16 (alias, post-mainloop)
    int*   redi    = (int*)(Bs + 128 * 16);         // 128*16 (alias)

    const int tid = threadIdx.x;
    const int tx  = tid & 15;
    const int ty  = tid >> 4;

    const int w  = blockIdx.x;
    int u        = (int)(((long long)w       * NUNITS) / NWORK);
    const int u1 = (int)(((long long)(w + 1) * NUNITS) / NWORK);

    while (u < u1) {
        const int rt   = u >> 4;
        const int c0   = u & 15;
        const int cend = min(NCHUNK, c0 + (u1 - u));
        const int rowBase = rt * 128;

        // ---- load A tile (128 rows x 128 f32), row-major, unpadded ----
        __syncthreads();                           // As may be live from epilogue
        {
            const float4* gin = (const float4*)(in + (size_t)rowBase * DIM);
            float4* As4 = (float4*)As;
            #pragma unroll
            for (int i = 0; i < 16; i++)
                As4[tid + i * 256] = gin[tid + i * 256];
        }
        __syncthreads();

        // ---- per-row sum of squares (sequential order) ----
        if (tid < 128) {
            float s = 0.0f;
            const float* ar = As + tid * 128;
            for (int d = 0; d < DIM; d++) {
                float v = ar[d];
                s = __fadd_rn(s, __fmul_rn(v, v));
            }
            rows2_s[tid] = s;
        }

        float minv[8];
        int   mini[8];
        #pragma unroll
        for (int r = 0; r < 8; r++) { minv[r] = 3.4e38f; mini[r] = 0x7fffffff; }

        // ---- loop over this worker's chunks of the rowtile ----
        for (int ch = c0; ch < cend; ch++) {
            __syncthreads();                      // protect csum_s/Bs rewrite
            {
                const float4* gb = (const float4*)(cb + (size_t)ch * 64 * DIM);
                #pragma unroll
                for (int i = 0; i < 8; i++) {
                    int idx = tid + i * 256;      // 0..2047
                    int r = idx >> 5, c = idx & 31;
                    ((float4*)(Bs + r * B_STRIDE))[c] = gb[idx];
                }
                if (tid < 64) csum_s[tid] = g_csum2[ch * 64 + tid];
            }
            __syncthreads();

            unsigned long long acc[8][4];
            #pragma unroll
            for (int r = 0; r < 8; r++)
                #pragma unroll
                for (int j = 0; j < 4; j++) acc[r][j] = 0ULL;

            const ulonglong2* A2 = (const ulonglong2*)As + (size_t)(ty * 8) * 32;
            const ulonglong2* B2 = (const ulonglong2*)Bs;

            #pragma unroll 4
            for (int dq = 0; dq < 32; dq++) {     // 4 dims per iter
                ulonglong2 b[4];
                #pragma unroll
                for (int j = 0; j < 4; j++)
                    b[j] = B2[(tx + 16 * j) * 33 + dq];
                #pragma unroll
                for (int r = 0; r < 8; r++) {
                    ulonglong2 a = A2[r * 32 + dq];
                    #pragma unroll
                    for (int j = 0; j < 4; j++) {
                        acc[r][j] = ffma2(a.x, b[j].x, acc[r][j]);
                        acc[r][j] = ffma2(a.y, b[j].y, acc[r][j]);
                    }
                }
            }

            // chunk epilogue: running argmin (ascending index, strict <)
            #pragma unroll
            for (int r = 0; r < 8; r++) {
                float t = rows2_s[ty * 8 + r];
                #pragma unroll
                for (int j = 0; j < 4; j++) {
                    float2 s = u2f2(acc[r][j]);
                    float dot = __fadd_rn(s.x, s.y);
                    float dist = __fsub_rn(__fadd_rn(t, csum_s[tx + 16 * j]),
                                           __fmul_rn(2.0f, dot));
                    int cod = ch * 64 + tx + 16 * j;
                    if (dist < minv[r]) { minv[r] = dist; mini[r] = cod; }
                }
            }
        }

        // ---- cross-thread lexicographic partial argmin, flush to global ----
        __syncthreads();                           // Bs reusable
        #pragma unroll
        for (int r = 0; r < 8; r++) {
            int lr = ty * 8 + r;
            redv[lr * 16 + tx] = minv[r];
            redi[lr * 16 + tx] = mini[r];
        }
        __syncthreads();
        if (tid < 128) {
            float bv = 3.5e38f;
            int   bi = 0x7fffffff;
            #pragma unroll
            for (int t2 = 0; t2 < 16; t2++) {
                float v = redv[tid * 16 + t2];
                int   i2 = redi[tid * 16 + t2];
                if (v < bv || (v == bv && i2 < bi)) { bv = v; bi = i2; }
            }
            unsigned long long pk =
                ((unsigned long long)__float_as_uint(bv) << 32) |
                (unsigned int)bi;
            atomicMin(&g_best[rowBase + tid], pk);
            __threadfence();                       // release our contribution
        }
        __syncthreads();
        if (tid == 0) {
            int old = atomicAdd(&g_chunkcnt[rt], cend - c0);
            flag_s[0] = (old + (cend - c0) == NCHUNK) ? 1 : 0;
        }
        __syncthreads();

        // ---- rowtile finisher runs the fused output epilogue ----
        if (flag_s[0]) {
            __threadfence();                       // acquire all contributions
            if (tid < 128) {
                unsigned long long pk = __ldcg(&g_best[rowBase + tid]);
                int bi = (int)(pk & 0xffffffffu);
                besti_s[tid] = bi;
                atomicAdd(&g_counts[bi], 1);
            }
            __syncthreads();

            // quantized write + loss partial (As still holds this rowtile)
            float ls = 0.0f;
            float* outq = out + 1;                 // quantized at element 1
            #pragma unroll 4
            for (int i = 0; i < 64; i++) {
                int idx = tid + i * 256;           // 0..16383
                int lr = idx >> 7, d = idx & 127;
                float q = __ldg(&cb[(size_t)besti_s[lr] * DIM + d]);
                float x = As[lr * 128 + d];
                float df = x - q;
                ls = fmaf(df, df, ls);
                outq[(size_t)(rowBase + lr) * DIM + d] = q;
            }
            #pragma unroll
            for (int o = 16; o; o >>= 1)
                ls += __shfl_down_sync(0xffffffffu, ls, o);
            if ((tid & 31) == 0) atomicAdd(&g_loss, (double)ls);

            // one-hot encodings (region starts at elem 8388610: 8B-aligned)
            float2* enc2 = (float2*)(out + 2 + (size_t)NROWS * DIM);
            #pragma unroll 4
            for (int i = 0; i < 256; i++) {
                int idx = tid + i * 256;           // 0..65535 float2s
                int lr = idx >> 9, p = idx & 511;
                int bi = besti_s[lr];
                int c1 = p * 2;
                float2 v;
                v.x = (c1     == bi) ? 1.0f : 0.0f;
                v.y = (c1 + 1 == bi) ? 1.0f : 0.0f;
                enc2[(size_t)(rowBase + lr) * 512 + p] = v;
            }
        }

        u = (rt << 4) + cend;
    }
}

__global__ void vq_final(float* __restrict__ out) {
    __shared__ float sh[KCB];
    int t = threadIdx.x;
    float p = (float)g_counts[t] * (1.0f / 65536.0f);
    sh[t] = __fmul_rn(p, logf(__fadd_rn(p, 1e-10f)));
    __syncthreads();
    for (int s = 512; s; s >>= 1) {
        if (t < s) sh[t] += sh[t + s];
        __syncthreads();
    }
    if (t == 0) {
        out[1 + (size_t)NROWS * DIM] = expf(-sh[0]);     // perplexity
        double m = g_loss * (1.0 / ((double)NROWS * (double)DIM));
        out[0] = (float)(m + 0.25 * m);                  // loss = q + 0.25*e
    }
}

// ---------------- launch ----------------
extern "C" void kernel_launch(void* const* d_in, const int* in_sizes, int n_in,
                              void* d_out, int out_size) {
    const float* in = (const float*)d_in[0];
    const float* cb = (const float*)d_in[1];
    float* out = (float*)d_out;

    const size_t SMEM = (size_t)(128 * 128 + 64 * B_STRIDE + 128 + 64 + 128 + 4) * 4;
    cudaFuncSetAttribute(vq_main, cudaFuncAttributeMaxDynamicSharedMemorySize, (int)SMEM);

    vq_prep<<<64, 256>>>(cb);
    vq_main<<<NWORK, 256, SMEM>>>(in, cb, out);
    vq_final<<<1, 1024>>>(out);
}

// round 8
// speedup vs baseline: 1.7303x; 1.7303x over previous
#include <cuda_runtime.h>

#define NROWS 65536
#define DIM   128
#define KCB   1024
#define NTILES 512            // row tiles of 128
#define NCHUNK 16             // K chunks of 64 codes
#define NUNITS (NTILES * NCHUNK)
#define NWORK  304            // persistent workers (152 SM x 2)

// ---------------- device scratch (no allocations allowed) ----------------
__device__ float              g_csum2[KCB];
__device__ int                g_counts[KCB];
__device__ double             g_loss;
__device__ unsigned long long g_best[NROWS];     // (dist_bits<<32)|code, atomicMin

// ---------------- helpers ----------------
__device__ __forceinline__ unsigned long long ffma2(unsigned long long a,
                                                    unsigned long long b,
                                                    unsigned long long c) {
    unsigned long long d;
    asm("fma.rn.f32x2 %0, %1, %2, %3;" : "=l"(d) : "l"(a), "l"(b), "l"(c));
    return d;
}

__device__ __forceinline__ float2 u2f2(unsigned long long v) {
    union { unsigned long long u; float2 f; } cvt;
    cvt.u = v;
    return cvt.f;
}

// ---------------- prep: init scratch + codebook row sums (warp per row) ----
__global__ void __launch_bounds__(256) vq_prep(const float* __restrict__ cb) {
    int gid = blockIdx.x * 256 + threadIdx.x;        // grid 256 -> 65536 threads
    g_best[gid] = 0xFFFFFFFFFFFFFFFFULL;
    int w = gid >> 5, l = gid & 31;
    if (w < KCB) {
        float4 v = ((const float4*)cb)[w * 32 + l];  // coalesced: row w, cols 4l..4l+3
        float s = __fmul_rn(v.x, v.x);
        s = __fadd_rn(s, __fmul_rn(v.y, v.y));
        s = __fadd_rn(s, __fmul_rn(v.z, v.z));
        s = __fadd_rn(s, __fmul_rn(v.w, v.w));
        #pragma unroll
        for (int o = 16; o; o >>= 1)
            s += __shfl_xor_sync(0xffffffffu, s, o);
        if (l == 0) g_csum2[w] = s;
    }
    if (gid < KCB) g_counts[gid] = 0;
    if (gid == 0) g_loss = 0.0;
}

// ---------------- main persistent kernel: pure GEMM + argmin + flush -------
// 304 workers x 256 threads, 2 CTAs/SM. Unit = (rowtile of 128) x (chunk of 64).
// Worker w owns contiguous units [w*NUNITS/NWORK, (w+1)*NUNITS/NWORK).
// Thread tile: 8 rows x 4 codes, f32x2 packed along D.
#define B_STRIDE 132

__global__ void __launch_bounds__(256, 2)
vq_main(const float* __restrict__ in, const float* __restrict__ cb) {
    extern __shared__ float smem[];
    float* As      = smem;                          // 128*128 floats (unpadded)
    float* Bs      = smem + 128 * 128;              // 64*132 floats (reused for reduce)
    float* rows2_s = Bs + 64 * B_STRIDE;            // 128
    float* csum_s  = rows2_s + 128;                 // 64
    float* redv    = Bs;                            // 128*16 (alias, post-mainloop)
    int*   redi    = (int*)(Bs + 128 * 16);         // 128*16 (alias)

    const int tid = threadIdx.x;
    const int tx  = tid & 15;
    const int ty  = tid >> 4;

    const int w  = blockIdx.x;
    int u        = (int)(((long long)w       * NUNITS) / NWORK);
    const int u1 = (int)(((long long)(w + 1) * NUNITS) / NWORK);

    while (u < u1) {
        const int rt   = u >> 4;
        const int c0   = u & 15;
        const int cend = min(NCHUNK, c0 + (u1 - u));
        const int rowBase = rt * 128;

        // ---- load A tile (128 rows x 128 f32), row-major, unpadded ----
        __syncthreads();                           // Bs/redv still live from prev flush
        {
            const float4* gin = (const float4*)(in + (size_t)rowBase * DIM);
            float4* As4 = (float4*)As;
            #pragma unroll
            for (int i = 0; i < 16; i++)
                As4[tid + i * 256] = gin[tid + i * 256];
        }
        __syncthreads();

        // ---- per-row sum of squares (sequential order) ----
        if (tid < 128) {
            float s = 0.0f;
            const float* ar = As + tid * 128;
            for (int d = 0; d < DIM; d++) {
                float v = ar[d];
                s = __fadd_rn(s, __fmul_rn(v, v));
            }
            rows2_s[tid] = s;
        }

        float minv[8];
        int   mini[8];
        #pragma unroll
        for (int r = 0; r < 8; r++) { minv[r] = 3.4e38f; mini[r] = 0x7fffffff; }

        // ---- chunks owned by this worker within the rowtile ----
        for (int ch = c0; ch < cend; ch++) {
            __syncthreads();                      // protect csum_s/Bs rewrite
            {
                const float4* gb = (const float4*)(cb + (size_t)ch * 64 * DIM);
                #pragma unroll
                for (int i = 0; i < 8; i++) {
                    int idx = tid + i * 256;      // 0..2047
                    int r = idx >> 5, c = idx & 31;
                    ((float4*)(Bs + r * B_STRIDE))[c] = gb[idx];
                }
                if (tid < 64) csum_s[tid] = g_csum2[ch * 64 + tid];
            }
            __syncthreads();

            unsigned long long acc[8][4];
            #pragma unroll
            for (int r = 0; r < 8; r++)
                #pragma unroll
                for (int j = 0; j < 4; j++) acc[r][j] = 0ULL;

            const ulonglong2* A2 = (const ulonglong2*)As + (size_t)(ty * 8) * 32;
            const ulonglong2* B2 = (const ulonglong2*)Bs;

            #pragma unroll 4
            for (int dq = 0; dq < 32; dq++) {     // 4 dims per iter
                ulonglong2 b[4];
                #pragma unroll
                for (int j = 0; j < 4; j++)
                    b[j] = B2[(tx + 16 * j) * 33 + dq];
                #pragma unroll
                for (int r = 0; r < 8; r++) {
                    ulonglong2 a = A2[r * 32 + dq];
                    #pragma unroll
                    for (int j = 0; j < 4; j++) {
                        acc[r][j] = ffma2(a.x, b[j].x, acc[r][j]);
                        acc[r][j] = ffma2(a.y, b[j].y, acc[r][j]);
                    }
                }
            }

            // chunk epilogue: running argmin (ascending index, strict <)
            #pragma unroll
            for (int r = 0; r < 8; r++) {
                float t = rows2_s[ty * 8 + r];
                #pragma unroll
                for (int j = 0; j < 4; j++) {
                    float2 s = u2f2(acc[r][j]);
                    float dot = __fadd_rn(s.x, s.y);
                    float dist = __fsub_rn(__fadd_rn(t, csum_s[tx + 16 * j]),
                                           __fmul_rn(2.0f, dot));
                    int cod = ch * 64 + tx + 16 * j;
                    if (dist < minv[r]) { minv[r] = dist; mini[r] = cod; }
                }
            }
        }

        // ---- cross-thread lexicographic partial argmin -> atomicMin flush ----
        __syncthreads();                           // Bs reusable
        #pragma unroll
        for (int r = 0; r < 8; r++) {
            int lr = ty * 8 + r;
            redv[lr * 16 + tx] = minv[r];
            redi[lr * 16 + tx] = mini[r];
        }
        __syncthreads();
        if (tid < 128) {
            float bv = 3.5e38f;
            int   bi = 0x7fffffff;
            #pragma unroll
            for (int t2 = 0; t2 < 16; t2++) {
                float v = redv[tid * 16 + t2];
                int   i2 = redi[tid * 16 + t2];
                if (v < bv || (v == bv && i2 < bi)) { bv = v; bi = i2; }
            }
            unsigned long long pk =
                ((unsigned long long)__float_as_uint(bv) << 32) |
                (unsigned int)bi;
            atomicMin(&g_best[rowBase + tid], pk);
        }

        u = (rt << 4) + cend;
    }
}

// ---------------- output epilogue: warp per row -----------------------------
__global__ void __launch_bounds__(256)
vq_epi(const float* __restrict__ in, const float* __restrict__ cb,
       float* __restrict__ out) {
    __shared__ float blksum[8];
    const int tid = threadIdx.x;
    const int wid = tid >> 5, l = tid & 31;
    const int row = blockIdx.x * 8 + wid;                  // grid 8192 -> 65536 rows

    const int bi = (int)(g_best[row] & 0xffffffffu);
    if (l == 0) atomicAdd(&g_counts[bi], 1);

    // quantized (scalar stores: out+1 is only 4B-aligned) + loss partial
    float4 q = ((const float4*)(cb + (size_t)bi  * DIM))[l];
    float4 x = ((const float4*)(in + (size_t)row * DIM))[l];
    float* outq = out + 1 + (size_t)row * DIM + l * 4;
    outq[0] = q.x; outq[1] = q.y; outq[2] = q.z; outq[3] = q.w;
    float d0 = x.x - q.x, d1 = x.y - q.y, d2 = x.z - q.z, d3 = x.w - q.w;
    float ls = d0 * d0;
    ls = fmaf(d1, d1, ls);
    ls = fmaf(d2, d2, ls);
    ls = fmaf(d3, d3, ls);
    #pragma unroll
    for (int o = 16; o; o >>= 1)
        ls += __shfl_xor_sync(0xffffffffu, ls, o);
    if (l == 0) blksum[wid] = ls;

    // one-hot encodings (base elem 8388610: 8B-aligned -> float2)
    float2* enc = (float2*)(out + 2 + (size_t)NROWS * DIM) + (size_t)row * 512;
    #pragma unroll
    for (int k = 0; k < 16; k++) {
        int p = l + k * 32;
        int c0 = p * 2;
        float2 v;
        v.x = (c0     == bi) ? 1.0f : 0.0f;
        v.y = (c0 + 1 == bi) ? 1.0f : 0.0f;
        enc[p] = v;
    }

    __syncthreads();
    if (tid == 0) {
        double s = 0.0;
        #pragma unroll
        for (int i = 0; i < 8; i++) s += (double)blksum[i];
        atomicAdd(&g_loss, s);
    }
}

__global__ void vq_final(float* __restrict__ out) {
    __shared__ float sh[KCB];
    int t = threadIdx.x;
    float p = (float)g_counts[t] * (1.0f / 65536.0f);
    sh[t] = __fmul_rn(p, logf(__fadd_rn(p, 1e-10f)));
    __syncthreads();
    for (int s = 512; s; s >>= 1) {
        if (t < s) sh[t] += sh[t + s];
        __syncthreads();
    }
    if (t == 0) {
        out[1 + (size_t)NROWS * DIM] = expf(-sh[0]);     // perplexity
        double m = g_loss * (1.0 / ((double)NROWS * (double)DIM));
        out[0] = (float)(m + 0.25 * m);                  // loss = q + 0.25*e
    }
}

// ---------------- launch ----------------
extern "C" void kernel_launch(void* const* d_in, const int* in_sizes, int n_in,
                              void* d_out, int out_size) {
    const float* in = (const float*)d_in[0];
    const float* cb = (const float*)d_in[1];
    float* out = (float*)d_out;

    const size_t SMEM = (size_t)(128 * 128 + 64 * B_STRIDE + 128 + 64) * 4;
    cudaFuncSetAttribute(vq_main, cudaFuncAttributeMaxDynamicSharedMemorySize, (int)SMEM);

    vq_prep<<<256, 256>>>(cb);
    vq_main<<<NWORK, 256, SMEM>>>(in, cb);
    vq_epi<<<8192, 256>>>(in, cb, out);
    vq_final<<<1, 1024>>>(out);
}